// round 5
// baseline (speedup 1.0000x reference)
#include <cuda_runtime.h>

#define NB 8
#define NT 4095
#define NS 2048
#define ND 300
#define ND4 75            // ND / 4
#define PAD_IDX 1
#define NBLK 128          // scan blocks per batch
#define RPB 16            // rows per scan block
#define SUB 8             // rows per ty group

// ---- scratch (static __device__, no allocations) ----
__device__ __align__(16) int    g_leaves[NB * NS];
__device__ __align__(16) float  g_prefix[(long)NB * (NS + 1) * ND];  // exclusive prefix
__device__ __align__(16) float4 g_agg [NB * NBLK * ND4];             // block aggregates
__device__ __align__(16) float4 g_pref[NB * NBLK * ND4];             // block inclusive prefixes
__device__ int g_stat[NB * NBLK];                                    // 0=empty 1=agg 2=prefix

// ---------------------------------------------------------------------------
// 1) Pack leaves + zero lookback status.
// ---------------------------------------------------------------------------
__global__ void pack_kernel(const int* __restrict__ x, const int2* __restrict__ idx) {
    const int b = blockIdx.x;
    const int tid = threadIdx.x;
    const int lane = tid & 31;
    const int w = tid >> 5;
    __shared__ int warp_sums[32];
    __shared__ int s_base;
    if (tid == 0) s_base = 0;
    if (tid < NBLK) g_stat[b * NBLK + tid] = 0;   // reset lookback state each launch
    __syncthreads();

    #pragma unroll
    for (int start = 0; start < 4096; start += 1024) {
        int t = start + tid;
        int flag = 0;
        int tok = PAD_IDX;
        if (t < NT) {
            tok = x[b * NT + t];
            int2 lh = idx[b * NT + t];
            flag = (lh.x == lh.y && tok != PAD_IDX) ? 1 : 0;
        }
        unsigned m = __ballot_sync(0xffffffffu, flag);
        int within = __popc(m & ((1u << lane) - 1u));
        if (lane == 0) warp_sums[w] = __popc(m);
        __syncthreads();
        int woff = 0, tot = 0;
        #pragma unroll
        for (int i = 0; i < 32; i++) {
            int ws = warp_sums[i];
            if (i < w) woff += ws;
            tot += ws;
        }
        int pos = s_base + woff + within;
        if (flag && pos < NS) g_leaves[b * NS + pos] = tok;
        __syncthreads();
        if (tid == 0) s_base += tot;
        __syncthreads();
    }
    for (int p = s_base + tid; p < NS; p += 1024) g_leaves[b * NS + p] = PAD_IDX;
}

// ---------------------------------------------------------------------------
// 2) Fused single-pass exclusive prefix over packed leaf embeddings.
//    Decoupled lookback. grid (NBLK, NB), block (75, 2) = 150 threads.
//    ALL 1024 blocks are resident simultaneously (7 blocks/SM x 148 SMs),
//    so lookback spin cannot deadlock regardless of scheduling order.
// ---------------------------------------------------------------------------
__device__ __forceinline__ float4 f4add(float4 a, float4 b) {
    a.x += b.x; a.y += b.y; a.z += b.z; a.w += b.w; return a;
}

__global__ __launch_bounds__(150, 7) void scan_kernel(const float4* __restrict__ W4) {
    const int blk = blockIdx.x;       // 0..NBLK-1 (chain order within batch)
    const int b   = blockIdx.y;
    const int j   = threadIdx.x;      // 0..74 float4 lane over D
    const int ty  = threadIdx.y;      // 0..1 sub-chunk
    const int tid = ty * 75 + j;

    __shared__ float4 s_sum[2][ND4];
    __shared__ int s_st;

    const int row0 = blk * RPB + ty * SUB;
    const int4* lv = (const int4*)&g_leaves[b * NS + row0];
    const int4 l0 = lv[0], l1 = lv[1];

    // ---- phase 1: sub-chunk sum (gathers W rows; they stay hot in L1) ----
    float4 s;
    {
        float4 v0 = __ldg(&W4[(long)l0.x * ND4 + j]);
        float4 v1 = __ldg(&W4[(long)l0.y * ND4 + j]);
        float4 v2 = __ldg(&W4[(long)l0.z * ND4 + j]);
        float4 v3 = __ldg(&W4[(long)l0.w * ND4 + j]);
        float4 v4 = __ldg(&W4[(long)l1.x * ND4 + j]);
        float4 v5 = __ldg(&W4[(long)l1.y * ND4 + j]);
        float4 v6 = __ldg(&W4[(long)l1.z * ND4 + j]);
        float4 v7 = __ldg(&W4[(long)l1.w * ND4 + j]);
        s = f4add(f4add(f4add(v0, v1), f4add(v2, v3)),
                  f4add(f4add(v4, v5), f4add(v6, v7)));
    }
    s_sum[ty][j] = s;
    __syncthreads();
    const float4 c0 = s_sum[0][j];
    const float4 c1 = s_sum[1][j];
    const float4 agg = f4add(c0, c1);
    float4 off = {0.f, 0.f, 0.f, 0.f};
    if (ty == 1) off = c0;

    const int sidx = b * NBLK + blk;
    float4 run = {0.f, 0.f, 0.f, 0.f};

    if (blk == 0) {
        __stcg(&g_pref[sidx * ND4 + j], agg);
        __threadfence();
        __syncthreads();
        if (tid == 0) atomicExch(&g_stat[sidx], 2);
    } else {
        __stcg(&g_agg[sidx * ND4 + j], agg);
        __threadfence();
        __syncthreads();
        if (tid == 0) atomicExch(&g_stat[sidx], 1);

        // ---- lookback ----
        int p = sidx - 1;
        while (true) {
            if (tid == 0) {
                int st = atomicAdd(&g_stat[p], 0);
                while (st == 0) { __nanosleep(40); st = atomicAdd(&g_stat[p], 0); }
                s_st = st;
            }
            __syncthreads();
            const int st = s_st;
            __threadfence();   // acquire: payload stores precede status per producer fence
            float4 pay = (st == 2) ? __ldcg(&g_pref[p * ND4 + j])
                                   : __ldcg(&g_agg [p * ND4 + j]);
            run = f4add(run, pay);
            __syncthreads();   // protect s_st reuse
            if (st == 2) break;
            p--;
        }
        __stcg(&g_pref[sidx * ND4 + j], f4add(run, agg));
        __threadfence();
        __syncthreads();
        if (tid == 0) atomicExch(&g_stat[sidx], 2);
    }

    // ---- phase 3: write exclusive prefix rows (re-gather hits L1) ----
    float4 acc = f4add(run, off);
    float4 v0 = __ldg(&W4[(long)l0.x * ND4 + j]);
    float4 v1 = __ldg(&W4[(long)l0.y * ND4 + j]);
    float4 v2 = __ldg(&W4[(long)l0.z * ND4 + j]);
    float4 v3 = __ldg(&W4[(long)l0.w * ND4 + j]);
    float4 v4 = __ldg(&W4[(long)l1.x * ND4 + j]);
    float4 v5 = __ldg(&W4[(long)l1.y * ND4 + j]);
    float4 v6 = __ldg(&W4[(long)l1.z * ND4 + j]);
    float4 v7 = __ldg(&W4[(long)l1.w * ND4 + j]);

    float4* P = &((float4*)g_prefix)[((long)b * (NS + 1) + row0) * ND4 + j];
    P[0 * ND4] = acc; acc = f4add(acc, v0);
    P[1 * ND4] = acc; acc = f4add(acc, v1);
    P[2 * ND4] = acc; acc = f4add(acc, v2);
    P[3 * ND4] = acc; acc = f4add(acc, v3);
    P[4 * ND4] = acc; acc = f4add(acc, v4);
    P[5 * ND4] = acc; acc = f4add(acc, v5);
    P[6 * ND4] = acc; acc = f4add(acc, v6);
    P[7 * ND4] = acc; acc = f4add(acc, v7);
    if (blk == NBLK - 1 && ty == 1) P[8 * ND4] = acc;   // P[b][S][:]
}

// ---------------------------------------------------------------------------
// 3) Query. Leaf rows (lo==hi): out = W[leaves[lo]] directly (exact, 1 read).
//    Internal rows: out = (P[hi+1] - P[lo]) / denom.
// ---------------------------------------------------------------------------
__global__ void out_kernel(const int2* __restrict__ idxp,
                           const float4* __restrict__ W4,
                           float4* __restrict__ out) {
    const float4* __restrict__ P4 = (const float4*)g_prefix;
    int i = blockIdx.x * blockDim.x + threadIdx.x;
    if (i >= NB * NT * ND4) return;
    int bt = i / ND4;
    int j = i - bt * ND4;
    int b = bt / NT;
    int2 lh = idxp[bt];
    if (lh.x == lh.y) {
        int leaf = g_leaves[b * NS + lh.x];
        out[i] = __ldg(&W4[(long)leaf * ND4 + j]);
        return;
    }
    int dn = lh.y - lh.x + 1;
    if (dn < 1) dn = 1;
    float inv = 1.0f / (float)dn;
    long base = (long)b * (NS + 1) * ND4;
    float4 a = __ldg(&P4[base + (long)(lh.y + 1) * ND4 + j]);
    float4 c = __ldg(&P4[base + (long)lh.x * ND4 + j]);
    float4 o;
    o.x = (a.x - c.x) * inv;
    o.y = (a.y - c.y) * inv;
    o.z = (a.z - c.z) * inv;
    o.w = (a.w - c.w) * inv;
    out[i] = o;
}

// ---------------------------------------------------------------------------
extern "C" void kernel_launch(void* const* d_in, const int* in_sizes, int n_in,
                              void* d_out, int out_size) {
    const int*  x   = (const int*)d_in[0];      // [B,T]   int32
    const int2* idx = (const int2*)d_in[1];     // [B,T,2] int32
    const float4* W4 = (const float4*)d_in[2];  // [V,D]   fp32
    float* out = (float*)d_out;                 // [B,T,D] fp32

    pack_kernel<<<NB, 1024>>>(x, idx);

    dim3 blk(75, 2);
    dim3 grd(NBLK, NB);                          // 1024 blocks, all resident
    scan_kernel<<<grd, blk>>>(W4);

    int n4 = NB * NT * ND4;
    out_kernel<<<(n4 + 255) / 256, 256>>>(idx, W4, (float4*)out);
}

// round 6
// speedup vs baseline: 1.5122x; 1.5122x over previous
#include <cuda_runtime.h>

#define NB 8
#define NT 4095
#define NS 2048
#define ND 300
#define ND4 75            // ND / 4
#define PAD_IDX 1
#define NCHUNK 64
#define CLEN 32           // NS / NCHUNK
#define NTILE 16          // pack tiles per batch (256 tokens each)
#define TILE 256

// ---- scratch (static __device__, no allocations) ----
__device__ __align__(16) int   g_leaves[NB * NS];
__device__ __align__(16) float g_prefix[(long)NB * (NS + 1) * ND];  // exclusive prefix
__device__ __align__(16) float g_csum[NB * NCHUNK * ND];
__device__ int g_cnt[NB * NTILE];

// ---------------------------------------------------------------------------
// 1a) Count leaves per 256-token tile.  grid (NTILE, NB), block 256.
// ---------------------------------------------------------------------------
__global__ void count_kernel(const int* __restrict__ x, const int2* __restrict__ idx) {
    const int tile = blockIdx.x, b = blockIdx.y;
    const int tid = threadIdx.x;
    const int t = tile * TILE + tid;
    int flag = 0;
    if (t < NT) {
        int tok = x[b * NT + t];
        int2 lh = idx[b * NT + t];
        flag = (lh.x == lh.y && tok != PAD_IDX) ? 1 : 0;
    }
    unsigned m = __ballot_sync(0xffffffffu, flag);
    __shared__ int ws[8];
    if ((tid & 31) == 0) ws[tid >> 5] = __popc(m);
    __syncthreads();
    if (tid == 0) {
        int s = 0;
        #pragma unroll
        for (int i = 0; i < 8; i++) s += ws[i];
        g_cnt[b * NTILE + tile] = s;
    }
}

// ---------------------------------------------------------------------------
// 1b) Scatter leaves.  grid (NTILE, NB), block 256.  Block offset = sum of
//     prior tile counts (16 ints, L2-hot); in-tile rank via ballot block scan.
// ---------------------------------------------------------------------------
__global__ void scatter_kernel(const int* __restrict__ x, const int2* __restrict__ idx) {
    const int tile = blockIdx.x, b = blockIdx.y;
    const int tid = threadIdx.x;
    const int lane = tid & 31;
    const int w = tid >> 5;
    const int t = tile * TILE + tid;

    int flag = 0, tok = PAD_IDX;
    if (t < NT) {
        tok = x[b * NT + t];
        int2 lh = idx[b * NT + t];
        flag = (lh.x == lh.y && tok != PAD_IDX) ? 1 : 0;
    }
    unsigned m = __ballot_sync(0xffffffffu, flag);
    int within = __popc(m & ((1u << lane) - 1u));
    __shared__ int ws[8];
    if (lane == 0) ws[w] = __popc(m);
    __syncthreads();
    int woff = 0;
    #pragma unroll
    for (int i = 0; i < 8; i++) if (i < w) woff += ws[i];

    int base = 0;
    #pragma unroll
    for (int i = 0; i < NTILE; i++) if (i < tile) base += __ldg(&g_cnt[b * NTILE + i]);

    int pos = base + woff + within;
    if (flag && pos < NS) g_leaves[b * NS + pos] = tok;
}

// ---------------------------------------------------------------------------
// 1c) Fill tail [total, NS) with PAD (W[PAD] row is zero).  grid NB.
// ---------------------------------------------------------------------------
__global__ void fill_kernel() {
    const int b = blockIdx.x;
    int total = 0;
    #pragma unroll
    for (int i = 0; i < NTILE; i++) total += __ldg(&g_cnt[b * NTILE + i]);
    for (int p = total + threadIdx.x; p < NS; p += blockDim.x)
        g_leaves[b * NS + p] = PAD_IDX;
}

// ---------------------------------------------------------------------------
// 2a) Chunk sums (float4 over d).  grid (NCHUNK/4, NB), block (75, 4).
// ---------------------------------------------------------------------------
__global__ __launch_bounds__(300) void chunksum_kernel(const float4* __restrict__ W4) {
    const int c = blockIdx.x * 4 + threadIdx.y;
    const int b = blockIdx.y;
    const int j = threadIdx.x;                 // 0..74
    const int* lv = &g_leaves[b * NS + c * CLEN];
    int leaf[CLEN];
    #pragma unroll
    for (int r = 0; r < CLEN; r++) leaf[r] = lv[r];

    float4 a0 = {0,0,0,0}, a1 = {0,0,0,0}, a2 = {0,0,0,0}, a3 = {0,0,0,0};
    #pragma unroll
    for (int r = 0; r < CLEN; r += 4) {
        float4 v0 = __ldg(&W4[(long)leaf[r + 0] * ND4 + j]);
        float4 v1 = __ldg(&W4[(long)leaf[r + 1] * ND4 + j]);
        float4 v2 = __ldg(&W4[(long)leaf[r + 2] * ND4 + j]);
        float4 v3 = __ldg(&W4[(long)leaf[r + 3] * ND4 + j]);
        a0.x += v0.x; a0.y += v0.y; a0.z += v0.z; a0.w += v0.w;
        a1.x += v1.x; a1.y += v1.y; a1.z += v1.z; a1.w += v1.w;
        a2.x += v2.x; a2.y += v2.y; a2.z += v2.z; a2.w += v2.w;
        a3.x += v3.x; a3.y += v3.y; a3.z += v3.z; a3.w += v3.w;
    }
    float4 s;
    s.x = (a0.x + a1.x) + (a2.x + a3.x);
    s.y = (a0.y + a1.y) + (a2.y + a3.y);
    s.z = (a0.z + a1.z) + (a2.z + a3.z);
    s.w = (a0.w + a1.w) + (a2.w + a3.w);
    ((float4*)g_csum)[(b * NCHUNK + c) * ND4 + j] = s;
}

// ---------------------------------------------------------------------------
// 2b) Scan chunk sums in place -> exclusive chunk offsets.
//     One WARP per (b,d): lane holds chunks (2*lane, 2*lane+1), shfl scan.
// ---------------------------------------------------------------------------
__global__ void chunkscan_kernel() {
    int gw = (blockIdx.x * blockDim.x + threadIdx.x) >> 5;
    int lane = threadIdx.x & 31;
    if (gw >= NB * ND) return;
    int b = gw / ND, d = gw - b * ND;

    float* base = &g_csum[b * NCHUNK * ND + d];
    float v0 = base[(2 * lane + 0) * ND];
    float v1 = base[(2 * lane + 1) * ND];
    float s = v0 + v1;

    float incl = s;
    #pragma unroll
    for (int off = 1; off < 32; off <<= 1) {
        float n = __shfl_up_sync(0xffffffffu, incl, off);
        if (lane >= off) incl += n;
    }
    float excl = incl - s;
    base[(2 * lane + 0) * ND] = excl;
    base[(2 * lane + 1) * ND] = excl + v0;
}

// ---------------------------------------------------------------------------
// 2c) Exclusive prefix P[b][r][:] (float4 over d); last chunk writes P[b][S].
// ---------------------------------------------------------------------------
__global__ __launch_bounds__(300) void prefix_kernel(const float4* __restrict__ W4) {
    const int c = blockIdx.x * 4 + threadIdx.y;
    const int b = blockIdx.y;
    const int j = threadIdx.x;                 // 0..74
    const int* lv = &g_leaves[b * NS + c * CLEN];
    int leaf[CLEN];
    #pragma unroll
    for (int r = 0; r < CLEN; r++) leaf[r] = lv[r];

    float4 acc = ((const float4*)g_csum)[(b * NCHUNK + c) * ND4 + j];
    float4* P = &((float4*)g_prefix)[((long)b * (NS + 1) + (long)c * CLEN) * ND4 + j];

    #pragma unroll
    for (int r = 0; r < CLEN; r += 4) {
        float4 v0 = __ldg(&W4[(long)leaf[r + 0] * ND4 + j]);
        float4 v1 = __ldg(&W4[(long)leaf[r + 1] * ND4 + j]);
        float4 v2 = __ldg(&W4[(long)leaf[r + 2] * ND4 + j]);
        float4 v3 = __ldg(&W4[(long)leaf[r + 3] * ND4 + j]);
        P[(long)(r + 0) * ND4] = acc;
        acc.x += v0.x; acc.y += v0.y; acc.z += v0.z; acc.w += v0.w;
        P[(long)(r + 1) * ND4] = acc;
        acc.x += v1.x; acc.y += v1.y; acc.z += v1.z; acc.w += v1.w;
        P[(long)(r + 2) * ND4] = acc;
        acc.x += v2.x; acc.y += v2.y; acc.z += v2.z; acc.w += v2.w;
        P[(long)(r + 3) * ND4] = acc;
        acc.x += v3.x; acc.y += v3.y; acc.z += v3.z; acc.w += v3.w;
    }
    if (c == NCHUNK - 1) P[(long)CLEN * ND4] = acc;   // P[b][S][:]
}

// ---------------------------------------------------------------------------
// 3) Query. Leaf rows (lo==hi): out = W[leaves[lo]] directly.
//    Internal rows: out = (P[hi+1] - P[lo]) / denom.
// ---------------------------------------------------------------------------
__global__ void out_kernel(const int2* __restrict__ idxp,
                           const float4* __restrict__ W4,
                           float4* __restrict__ out) {
    const float4* __restrict__ P4 = (const float4*)g_prefix;
    int i = blockIdx.x * blockDim.x + threadIdx.x;
    if (i >= NB * NT * ND4) return;
    int bt = i / ND4;
    int j = i - bt * ND4;
    int b = bt / NT;
    int2 lh = idxp[bt];
    if (lh.x == lh.y) {
        int leaf = g_leaves[b * NS + lh.x];
        out[i] = __ldg(&W4[(long)leaf * ND4 + j]);
        return;
    }
    int dn = lh.y - lh.x + 1;
    if (dn < 1) dn = 1;
    float inv = 1.0f / (float)dn;
    long base = (long)b * (NS + 1) * ND4;
    float4 a = __ldg(&P4[base + (long)(lh.y + 1) * ND4 + j]);
    float4 c = __ldg(&P4[base + (long)lh.x * ND4 + j]);
    float4 o;
    o.x = (a.x - c.x) * inv;
    o.y = (a.y - c.y) * inv;
    o.z = (a.z - c.z) * inv;
    o.w = (a.w - c.w) * inv;
    out[i] = o;
}

// ---------------------------------------------------------------------------
extern "C" void kernel_launch(void* const* d_in, const int* in_sizes, int n_in,
                              void* d_out, int out_size) {
    const int*  x   = (const int*)d_in[0];      // [B,T]   int32
    const int2* idx = (const int2*)d_in[1];     // [B,T,2] int32
    const float4* W4 = (const float4*)d_in[2];  // [V,D]   fp32
    float* out = (float*)d_out;                 // [B,T,D] fp32

    dim3 gpack(NTILE, NB);
    count_kernel<<<gpack, TILE>>>(x, idx);
    scatter_kernel<<<gpack, TILE>>>(x, idx);
    fill_kernel<<<NB, 256>>>();

    dim3 blk(75, 4);
    dim3 gscan(NCHUNK / 4, NB);
    chunksum_kernel<<<gscan, blk>>>(W4);

    int nwarp = NB * ND;
    chunkscan_kernel<<<(nwarp * 32 + 255) / 256, 256>>>();

    prefix_kernel<<<gscan, blk>>>(W4);

    int n4 = NB * NT * ND4;
    out_kernel<<<(n4 + 255) / 256, 256>>>(idx, W4, (float4*)out);
}

// round 7
// speedup vs baseline: 1.6054x; 1.0616x over previous
#include <cuda_runtime.h>

#define NB 8
#define NT 4095
#define NS 2048
#define ND 300
#define ND4 75            // ND / 4
#define PAD_IDX 1
#define NCHUNK 64
#define CLEN 32           // NS / NCHUNK
#define SUB 8             // rows per ty group (CLEN / 4)
#define NTILE 16          // pack tiles per batch (256 tokens each)
#define TILE 256

// ---- scratch (static __device__, no allocations) ----
__device__ __align__(16) int   g_leaves[NB * NS];
__device__ __align__(16) float g_prefix[(long)NB * (NS + 1) * ND];  // exclusive prefix
__device__ __align__(16) float g_csum[NB * NCHUNK * ND];
__device__ int g_cnt[NB * NTILE];

__device__ __forceinline__ float4 f4add(float4 a, float4 b) {
    a.x += b.x; a.y += b.y; a.z += b.z; a.w += b.w; return a;
}

// ---------------------------------------------------------------------------
// 1a) Count leaves per 256-token tile.  grid (NTILE, NB), block 256.
// ---------------------------------------------------------------------------
__global__ void count_kernel(const int* __restrict__ x, const int2* __restrict__ idx) {
    const int tile = blockIdx.x, b = blockIdx.y;
    const int tid = threadIdx.x;
    const int t = tile * TILE + tid;
    int flag = 0;
    if (t < NT) {
        int tok = x[b * NT + t];
        int2 lh = idx[b * NT + t];
        flag = (lh.x == lh.y && tok != PAD_IDX) ? 1 : 0;
    }
    unsigned m = __ballot_sync(0xffffffffu, flag);
    __shared__ int ws[8];
    if ((tid & 31) == 0) ws[tid >> 5] = __popc(m);
    __syncthreads();
    if (tid == 0) {
        int s = 0;
        #pragma unroll
        for (int i = 0; i < 8; i++) s += ws[i];
        g_cnt[b * NTILE + tile] = s;
    }
}

// ---------------------------------------------------------------------------
// 1b) Scatter leaves.  grid (NTILE, NB), block 256.
// ---------------------------------------------------------------------------
__global__ void scatter_kernel(const int* __restrict__ x, const int2* __restrict__ idx) {
    const int tile = blockIdx.x, b = blockIdx.y;
    const int tid = threadIdx.x;
    const int lane = tid & 31;
    const int w = tid >> 5;
    const int t = tile * TILE + tid;

    int flag = 0, tok = PAD_IDX;
    if (t < NT) {
        tok = x[b * NT + t];
        int2 lh = idx[b * NT + t];
        flag = (lh.x == lh.y && tok != PAD_IDX) ? 1 : 0;
    }
    unsigned m = __ballot_sync(0xffffffffu, flag);
    int within = __popc(m & ((1u << lane) - 1u));
    __shared__ int ws[8];
    if (lane == 0) ws[w] = __popc(m);
    __syncthreads();
    int woff = 0;
    #pragma unroll
    for (int i = 0; i < 8; i++) if (i < w) woff += ws[i];

    int base = 0;
    #pragma unroll
    for (int i = 0; i < NTILE; i++) if (i < tile) base += __ldg(&g_cnt[b * NTILE + i]);

    int pos = base + woff + within;
    if (flag && pos < NS) g_leaves[b * NS + pos] = tok;
}

// ---------------------------------------------------------------------------
// 1c) Fill tail [total, NS) with PAD (W[PAD] row is zero).  grid NB.
// ---------------------------------------------------------------------------
__global__ void fill_kernel() {
    const int b = blockIdx.x;
    int total = 0;
    #pragma unroll
    for (int i = 0; i < NTILE; i++) total += __ldg(&g_cnt[b * NTILE + i]);
    for (int p = total + threadIdx.x; p < NS; p += blockDim.x)
        g_leaves[b * NS + p] = PAD_IDX;
}

// ---------------------------------------------------------------------------
// 2a) Chunk sums.  grid (NCHUNK, NB) = 512 blocks, block (75, 4):
//     each ty sums SUB=8 rows, shared reduce, ty0 writes.
// ---------------------------------------------------------------------------
__global__ __launch_bounds__(300) void chunksum_kernel(const float4* __restrict__ W4) {
    const int c = blockIdx.x, b = blockIdx.y;
    const int j = threadIdx.x;                 // 0..74
    const int ty = threadIdx.y;                // 0..3

    const int4* lv = (const int4*)&g_leaves[b * NS + c * CLEN + ty * SUB];
    const int4 l0 = lv[0], l1 = lv[1];

    float4 v0 = __ldg(&W4[(long)l0.x * ND4 + j]);
    float4 v1 = __ldg(&W4[(long)l0.y * ND4 + j]);
    float4 v2 = __ldg(&W4[(long)l0.z * ND4 + j]);
    float4 v3 = __ldg(&W4[(long)l0.w * ND4 + j]);
    float4 v4 = __ldg(&W4[(long)l1.x * ND4 + j]);
    float4 v5 = __ldg(&W4[(long)l1.y * ND4 + j]);
    float4 v6 = __ldg(&W4[(long)l1.z * ND4 + j]);
    float4 v7 = __ldg(&W4[(long)l1.w * ND4 + j]);

    float4 s = f4add(f4add(f4add(v0, v1), f4add(v2, v3)),
                     f4add(f4add(v4, v5), f4add(v6, v7)));

    __shared__ float4 s_sum[4][ND4];
    s_sum[ty][j] = s;
    __syncthreads();
    if (ty == 0) {
        float4 tot = f4add(f4add(s_sum[0][j], s_sum[1][j]),
                           f4add(s_sum[2][j], s_sum[3][j]));
        ((float4*)g_csum)[(b * NCHUNK + c) * ND4 + j] = tot;
    }
}

// ---------------------------------------------------------------------------
// 2b) Scan chunk sums in place -> exclusive chunk offsets.
//     One WARP per (b,d): lane holds chunks (2*lane, 2*lane+1), shfl scan.
// ---------------------------------------------------------------------------
__global__ void chunkscan_kernel() {
    int gw = (blockIdx.x * blockDim.x + threadIdx.x) >> 5;
    int lane = threadIdx.x & 31;
    if (gw >= NB * ND) return;
    int b = gw / ND, d = gw - b * ND;

    float* base = &g_csum[b * NCHUNK * ND + d];
    float v0 = base[(2 * lane + 0) * ND];
    float v1 = base[(2 * lane + 1) * ND];
    float s = v0 + v1;

    float incl = s;
    #pragma unroll
    for (int off = 1; off < 32; off <<= 1) {
        float n = __shfl_up_sync(0xffffffffu, incl, off);
        if (lane >= off) incl += n;
    }
    float excl = incl - s;
    base[(2 * lane + 0) * ND] = excl;
    base[(2 * lane + 1) * ND] = excl + v0;
}

// ---------------------------------------------------------------------------
// 2c) Exclusive prefix.  grid (NCHUNK, NB) = 512 blocks, block (75, 4):
//     each ty gathers its 8 rows once, sub-sums exchanged via shared,
//     each ty writes its 8 prefix rows.  Last (c,ty) writes P[b][S].
// ---------------------------------------------------------------------------
__global__ __launch_bounds__(300) void prefix_kernel(const float4* __restrict__ W4) {
    const int c = blockIdx.x, b = blockIdx.y;
    const int j = threadIdx.x;                 // 0..74
    const int ty = threadIdx.y;                // 0..3
    const int row0 = c * CLEN + ty * SUB;

    const int4* lv = (const int4*)&g_leaves[b * NS + row0];
    const int4 l0 = lv[0], l1 = lv[1];

    float4 v0 = __ldg(&W4[(long)l0.x * ND4 + j]);
    float4 v1 = __ldg(&W4[(long)l0.y * ND4 + j]);
    float4 v2 = __ldg(&W4[(long)l0.z * ND4 + j]);
    float4 v3 = __ldg(&W4[(long)l0.w * ND4 + j]);
    float4 v4 = __ldg(&W4[(long)l1.x * ND4 + j]);
    float4 v5 = __ldg(&W4[(long)l1.y * ND4 + j]);
    float4 v6 = __ldg(&W4[(long)l1.z * ND4 + j]);
    float4 v7 = __ldg(&W4[(long)l1.w * ND4 + j]);

    float4 s = f4add(f4add(f4add(v0, v1), f4add(v2, v3)),
                     f4add(f4add(v4, v5), f4add(v6, v7)));

    __shared__ float4 s_sum[4][ND4];
    s_sum[ty][j] = s;
    __syncthreads();

    float4 acc = ((const float4*)g_csum)[(b * NCHUNK + c) * ND4 + j];
    if (ty >= 1) acc = f4add(acc, s_sum[0][j]);
    if (ty >= 2) acc = f4add(acc, s_sum[1][j]);
    if (ty >= 3) acc = f4add(acc, s_sum[2][j]);

    float4* P = &((float4*)g_prefix)[((long)b * (NS + 1) + row0) * ND4 + j];
    P[0 * ND4] = acc; acc = f4add(acc, v0);
    P[1 * ND4] = acc; acc = f4add(acc, v1);
    P[2 * ND4] = acc; acc = f4add(acc, v2);
    P[3 * ND4] = acc; acc = f4add(acc, v3);
    P[4 * ND4] = acc; acc = f4add(acc, v4);
    P[5 * ND4] = acc; acc = f4add(acc, v5);
    P[6 * ND4] = acc; acc = f4add(acc, v6);
    P[7 * ND4] = acc; acc = f4add(acc, v7);
    if (c == NCHUNK - 1 && ty == 3) P[8 * ND4] = acc;   // P[b][S][:]
}

// ---------------------------------------------------------------------------
// 3) Query. Leaf rows (lo==hi): out = W[leaves[lo]] directly.
//    Internal rows: out = (P[hi+1] - P[lo]) / denom.
// ---------------------------------------------------------------------------
__global__ void out_kernel(const int2* __restrict__ idxp,
                           const float4* __restrict__ W4,
                           float4* __restrict__ out) {
    const float4* __restrict__ P4 = (const float4*)g_prefix;
    int i = blockIdx.x * blockDim.x + threadIdx.x;
    if (i >= NB * NT * ND4) return;
    int bt = i / ND4;
    int j = i - bt * ND4;
    int b = bt / NT;
    int2 lh = idxp[bt];
    if (lh.x == lh.y) {
        int leaf = g_leaves[b * NS + lh.x];
        out[i] = __ldg(&W4[(long)leaf * ND4 + j]);
        return;
    }
    int dn = lh.y - lh.x + 1;
    if (dn < 1) dn = 1;
    float inv = 1.0f / (float)dn;
    long base = (long)b * (NS + 1) * ND4;
    float4 a = __ldg(&P4[base + (long)(lh.y + 1) * ND4 + j]);
    float4 c = __ldg(&P4[base + (long)lh.x * ND4 + j]);
    float4 o;
    o.x = (a.x - c.x) * inv;
    o.y = (a.y - c.y) * inv;
    o.z = (a.z - c.z) * inv;
    o.w = (a.w - c.w) * inv;
    out[i] = o;
}

// ---------------------------------------------------------------------------
extern "C" void kernel_launch(void* const* d_in, const int* in_sizes, int n_in,
                              void* d_out, int out_size) {
    const int*  x   = (const int*)d_in[0];      // [B,T]   int32
    const int2* idx = (const int2*)d_in[1];     // [B,T,2] int32
    const float4* W4 = (const float4*)d_in[2];  // [V,D]   fp32
    float* out = (float*)d_out;                 // [B,T,D] fp32

    dim3 gpack(NTILE, NB);
    count_kernel<<<gpack, TILE>>>(x, idx);
    scatter_kernel<<<gpack, TILE>>>(x, idx);
    fill_kernel<<<NB, 256>>>();

    dim3 blk(75, 4);
    dim3 gfull(NCHUNK, NB);                     // 512 blocks
    chunksum_kernel<<<gfull, blk>>>(W4);

    int nwarp = NB * ND;
    chunkscan_kernel<<<(nwarp * 32 + 255) / 256, 256>>>();

    prefix_kernel<<<gfull, blk>>>(W4);

    int n4 = NB * NT * ND4;
    out_kernel<<<(n4 + 255) / 256, 256>>>(idx, W4, (float4*)out);
}